// round 11
// baseline (speedup 1.0000x reference)
#include <cuda_runtime.h>
#include <cuda_fp16.h>
#include <cstdint>

// Problem constants
#define B_   4
#define C_   256
#define H_   64
#define W_   64
#define HW_  4096
#define KK_  9
#define KD_  2304            // C*KK (GEMM K), reordered as k = kk*256 + c
#define NP_  16384           // B*HW (GEMM N)
#define G_   32
#define EPS_ 1e-5f

// ---------------- helpers ----------------
__device__ __forceinline__ uint32_t smem_to_u32(const void* p) {
    uint32_t a;
    asm("{ .reg .u64 t; cvta.to.shared.u64 t, %1; cvt.u32.u64 %0, t; }" : "=r"(a) : "l"(p));
    return a;
}
__device__ __forceinline__ void cp16(uint32_t saddr, const void* g) {
    asm volatile("cp.async.cg.shared.global [%0], [%1], 16;" :: "r"(saddr), "l"(g));
}
#define CP_COMMIT() asm volatile("cp.async.commit_group;" ::: "memory")
#define CP_WAIT(n)  asm volatile("cp.async.wait_group %0;" :: "n"(n) : "memory")

__device__ __forceinline__ void ldsm_x4(uint32_t* r, uint32_t addr) {
    asm volatile("ldmatrix.sync.aligned.m8n8.x4.shared.b16 {%0,%1,%2,%3}, [%4];"
                 : "=r"(r[0]), "=r"(r[1]), "=r"(r[2]), "=r"(r[3]) : "r"(addr));
}
__device__ __forceinline__ void mma_f16(float* d, const uint32_t* a, uint32_t b0, uint32_t b1) {
    asm volatile(
        "mma.sync.aligned.m16n8k16.row.col.f32.f16.f16.f32 "
        "{%0,%1,%2,%3}, {%4,%5,%6,%7}, {%8,%9}, {%0,%1,%2,%3};"
        : "+f"(d[0]), "+f"(d[1]), "+f"(d[2]), "+f"(d[3])
        : "r"(a[0]), "r"(a[1]), "r"(a[2]), "r"(a[3]), "r"(b0), "r"(b1));
}

// -------- scratch (device globals) --------
__device__ uint2   g_pos[B_ * KK_ * HW_];
__device__ float4  g_wt [B_ * KK_ * HW_];
__device__ __half  g_xt [(size_t)B_ * HW_ * C_];   // x transposed fp16: [b][hw][c], 8MB
__device__ __half  g_ah [C_ * KD_];                // weights fp16 [o][kk*256+c]
__device__ __half  g_bh [(size_t)NP_ * KD_];       // im2col fp16 [p][kk*256+c]
__device__ float   g_att[NP_];
__device__ float   g_gsum [B_ * G_];
__device__ float   g_gsum2[B_ * G_];
__device__ float   g_mean[B_ * G_];
__device__ float   g_istd[B_ * G_];

// ================== kernel 0: coords + weight convert merged ==================
__global__ void k_prep(const float* __restrict__ off, const float* __restrict__ wgt) {
    int bid = blockIdx.x;
    int tid = threadIdx.x;

    if (bid >= 576) {
        int wb = bid - 576;
        int o  = wb / 9;
        int kk = wb - o * 9;
        int c  = tid;
        g_ah[o * KD_ + kk * 256 + c] = __float2half_rn(wgt[(o * 256 + c) * 9 + kk]);
        return;
    }

    int bkk = bid >> 4;
    int hw  = (bid & 15) * 256 + tid;
    int b   = bkk / KK_;
    int kk  = bkk - b * KK_;
    int h   = hw >> 6;
    int w   = hw & 63;

    if (bid == 0) {
        if (tid < 128)      g_gsum [tid] = 0.0f;
        else                g_gsum2[tid - 128] = 0.0f;
    }

    float dy = off[(b * 18 + kk * 2    ) * HW_ + hw];
    float dx = off[(b * 18 + kk * 2 + 1) * HW_ + hw];

    float py = (float)h + (float)(kk / 3 - 1) + dy;
    float px = (float)w + (float)(kk % 3 - 1) + dx;

    float fy = floorf(py), fx = floorf(px);
    int iy0 = (int)fy, ix0 = (int)fx;
    float wy1 = py - fy, wy0 = 1.0f - wy1;
    float wx1 = px - fx, wx0 = 1.0f - wx1;

    bool vy0 = (iy0 >= 0)  && (iy0 < H_);
    bool vy1 = (iy0 >= -1) && (iy0 < H_ - 1);
    bool vx0 = (ix0 >= 0)  && (ix0 < W_);
    bool vx1 = (ix0 >= -1) && (ix0 < W_ - 1);

    float4 wt;
    wt.x = wy0 * wx0 * (float)(vy0 && vx0);
    wt.y = wy0 * wx1 * (float)(vy0 && vx1);
    wt.z = wy1 * wx0 * (float)(vy1 && vx0);
    wt.w = wy1 * wx1 * (float)(vy1 && vx1);

    int y0c = min(max(iy0, 0), H_ - 1);
    int y1c = min(max(iy0 + 1, 0), H_ - 1);
    int x0c = min(max(ix0, 0), W_ - 1);
    int x1c = min(max(ix0 + 1, 0), W_ - 1);

    unsigned p00 = (unsigned)(y0c * W_ + x0c);
    unsigned p01 = (unsigned)(y0c * W_ + x1c);
    unsigned p10 = (unsigned)(y1c * W_ + x0c);
    unsigned p11 = (unsigned)(y1c * W_ + x1c);

    int ci = bkk * HW_ + hw;
    g_pos[ci] = make_uint2(p00 | (p01 << 16), p10 | (p11 << 16));
    g_wt[ci]  = wt;
}

// ================== kernel 1: transpose x -> xT[b][hw][c] (fp16) ==================
__global__ void k_xpose(const float* __restrict__ x) {
    __shared__ float t[32][33];
    int b   = blockIdx.z;
    int hw0 = blockIdx.x * 32;
    int c0  = blockIdx.y * 32;
    int tx = threadIdx.x, ty = threadIdx.y;

    #pragma unroll
    for (int i = 0; i < 32; i += 8)
        t[ty + i][tx] = x[((size_t)(b * C_ + c0 + ty + i)) * HW_ + hw0 + tx];
    __syncthreads();
    #pragma unroll
    for (int i = 0; i < 32; i += 8)
        g_xt[((size_t)(b * HW_) + hw0 + ty + i) * C_ + c0 + tx] = __float2half_rn(t[tx][ty + i]);
}

// ================== kernel 2: im2col from fp16 xT + fused attention ==================
__global__ void k_im2col_att(const float* __restrict__ attw,
                             const float* __restrict__ attb) {
    __shared__ uint2  spos[8][KK_];
    __shared__ float4 swt [8][KK_];

    int b   = blockIdx.y;
    int hw0 = blockIdx.x * 8;
    int tid = threadIdx.x, wid = tid >> 5, lane = tid & 31;

    if (tid < 8 * KK_) {
        int pi = tid / KK_, kk = tid - pi * KK_;
        spos[pi][kk] = g_pos[(b * KK_ + kk) * HW_ + hw0 + pi];
        swt [pi][kk] = g_wt [(b * KK_ + kk) * HW_ + hw0 + pi];
    }
    __syncthreads();

    int p  = b * HW_ + hw0 + wid;
    int c8 = lane * 8;
    const __half* xtb = g_xt + (size_t)(b * HW_) * C_ + c8;
    __half* dst0 = g_bh + (size_t)p * KD_ + c8;

    float mx[8];
    #pragma unroll
    for (int j = 0; j < 8; ++j) mx[j] = -1e30f;

    #pragma unroll
    for (int kk = 0; kk < KK_; ++kk) {
        uint2 pos = spos[wid][kk];
        float4 wt = swt[wid][kk];
        uint4 ua = *(const uint4*)(xtb + (size_t)(pos.x & 0xFFFFu) * C_);
        uint4 ub = *(const uint4*)(xtb + (size_t)(pos.x >> 16)     * C_);
        uint4 uc = *(const uint4*)(xtb + (size_t)(pos.y & 0xFFFFu) * C_);
        uint4 ud = *(const uint4*)(xtb + (size_t)(pos.y >> 16)     * C_);
        const __half2* ha = (const __half2*)&ua;
        const __half2* hb = (const __half2*)&ub;
        const __half2* hc = (const __half2*)&uc;
        const __half2* hd = (const __half2*)&ud;

        float val[8];
        #pragma unroll
        for (int jj = 0; jj < 4; ++jj) {
            float2 fa = __half22float2(ha[jj]);
            float2 fb = __half22float2(hb[jj]);
            float2 fc = __half22float2(hc[jj]);
            float2 fd = __half22float2(hd[jj]);
            val[jj * 2]     = wt.x * fa.x + wt.y * fb.x + wt.z * fc.x + wt.w * fd.x;
            val[jj * 2 + 1] = wt.x * fa.y + wt.y * fb.y + wt.z * fc.y + wt.w * fd.y;
        }

        union { __half hh[8]; uint4 v; } u;
        #pragma unroll
        for (int j = 0; j < 8; ++j) {
            mx[j] = fmaxf(mx[j], val[j]);
            u.hh[j] = __float2half_rn(val[j]);
        }
        *(uint4*)(dst0 + kk * 256) = u.v;
    }

    float2 w0 = *(const float2*)&attw[c8];
    float2 w1 = *(const float2*)&attw[c8 + 2];
    float2 w2 = *(const float2*)&attw[c8 + 4];
    float2 w3 = *(const float2*)&attw[c8 + 6];
    float acc = w0.x * mx[0] + w0.y * mx[1] + w1.x * mx[2] + w1.y * mx[3]
              + w2.x * mx[4] + w2.y * mx[5] + w3.x * mx[6] + w3.y * mx[7];
    #pragma unroll
    for (int s = 16; s; s >>= 1) acc += __shfl_xor_sync(0xFFFFFFFFu, acc, s);
    if (lane == 0) g_att[p] = 1.0f / (1.0f + __expf(-(acc + attb[0])));
}

// ================== kernel 3: fp16 single-combo GEMM, 8 warps, 4-stage ==================
// CTA 128(M) x 128(N), K-tile 32, 256 threads (8 warps, 4Mx2N, warp tile 32x64),
// 4-stage cp.async ring, 80B-padded rows, 2 CTAs/SM.
// Stage: A[128x80B]=10240, B[128x80B]=10240 -> 20480B; 4 stages = 81920B.
#define STAGE_B 20480
#define NSTAGE  4
#define GEMM_SMEM (NSTAGE * STAGE_B)

__global__ __launch_bounds__(256, 2) void k_gemm(float* __restrict__ out) {
    extern __shared__ __align__(128) char smem[];
    uint32_t sbase = smem_to_u32(smem);
    int tid = threadIdx.x, wid = tid >> 5, lane = tid & 31;
    int warpM = wid >> 1, warpN = wid & 1;     // 4 x 2 warp grid, warp tile 32x64
    int p0 = blockIdx.x * 128;
    int m0 = blockIdx.y * 128;

    // ---- loader: 256 threads; r = tid>>1 (0..127), q = (tid&1)*2 chunk pair ----
    int r = tid >> 1, q = (tid & 1) * 2;
    const __half* pA = g_ah + (size_t)(m0 + r) * KD_ + q * 8;
    const __half* pB = g_bh + (size_t)(p0 + r) * KD_ + q * 8;
    uint32_t sA = (uint32_t)(r * 80 + q * 16);

#define LOAD_STAGE(sb) do {                                          \
    cp16((sb) + sA,          pA);                                    \
    cp16((sb) + sA + 16u,    pA + 8);                                \
    cp16((sb) + sA + 10240u, pB);                                    \
    cp16((sb) + sA + 10256u, pB + 8);                                \
    pA += 32; pB += 32;                                              \
    CP_COMMIT();                                                     \
} while (0)

    float acc[2][8][4];
    #pragma unroll
    for (int i = 0; i < 2; ++i)
        #pragma unroll
        for (int j = 0; j < 8; ++j)
            #pragma unroll
            for (int qq = 0; qq < 4; ++qq) acc[i][j][qq] = 0.0f;

    uint32_t laneoff = (uint32_t)((lane & 15) * 80 + ((lane >> 4) << 4));
    uint32_t aoff = (uint32_t)(warpM * 32 * 80) + laneoff;
    uint32_t boff = 10240u + (uint32_t)(warpN * 64 * 80) + laneoff;

    uint32_t cur = sbase;
    uint32_t nxt = sbase + 3u * STAGE_B;
    const uint32_t send = sbase + (uint32_t)NSTAGE * STAGE_B;

    LOAD_STAGE(sbase);
    LOAD_STAGE(sbase + STAGE_B);
    LOAD_STAGE(sbase + 2u * STAGE_B);

    for (int kt = 0; kt < 72; ++kt) {
        if (kt < 69) { CP_WAIT(2); } else { CP_WAIT(0); }
        __syncthreads();
        if (kt < 69) {
            LOAD_STAGE(nxt);
            nxt += STAGE_B; if (nxt == send) nxt = sbase;
        }

        #pragma unroll
        for (int ks = 0; ks < 2; ++ks) {
            uint32_t ah[2][4], bh[4][4];
            #pragma unroll
            for (int mt = 0; mt < 2; ++mt)
                ldsm_x4(ah[mt], cur + aoff + (uint32_t)(mt * 16 * 80 + ks * 32));
            #pragma unroll
            for (int ntp = 0; ntp < 4; ++ntp)
                ldsm_x4(bh[ntp], cur + boff + (uint32_t)(ntp * 16 * 80 + ks * 32));

            #pragma unroll
            for (int mt = 0; mt < 2; ++mt)
                #pragma unroll
                for (int ntp = 0; ntp < 4; ++ntp)
                    #pragma unroll
                    for (int hf = 0; hf < 2; ++hf)
                        mma_f16(acc[mt][ntp * 2 + hf], ah[mt], bh[ntp][hf], bh[ntp][hf + 2]);
        }
        cur += STAGE_B; if (cur == send) cur = sbase;
    }

    // epilogue: multiply by att, write out, accumulate GroupNorm partial sums
    int b   = p0 >> 12;
    int hw0 = p0 & 4095;
    int qrow = lane >> 2, qcol = (lane & 3) * 2;

    #pragma unroll
    for (int mt = 0; mt < 2; ++mt) {
        float s0 = 0.0f, s20 = 0.0f, s1 = 0.0f, s21 = 0.0f;
        #pragma unroll
        for (int nt = 0; nt < 8; ++nt) {
            int n = warpN * 64 + nt * 8 + qcol;
            float2 av = *(const float2*)&g_att[p0 + n];
            int o = m0 + warpM * 32 + mt * 16 + qrow;
            float* base0 = out + ((size_t)(b * C_ + o)) * HW_ + hw0 + n;
            float* base1 = base0 + 8 * HW_;
            float2 v0, v1;
            v0.x = acc[mt][nt][0] * av.x;  v0.y = acc[mt][nt][1] * av.y;
            v1.x = acc[mt][nt][2] * av.x;  v1.y = acc[mt][nt][3] * av.y;
            *(float2*)base0 = v0;
            *(float2*)base1 = v1;
            s0 += v0.x + v0.y;  s20 += v0.x * v0.x + v0.y * v0.y;
            s1 += v1.x + v1.y;  s21 += v1.x * v1.x + v1.y * v1.y;
        }
        #pragma unroll
        for (int s = 16; s; s >>= 1) {
            s0  += __shfl_xor_sync(0xFFFFFFFFu, s0,  s);
            s20 += __shfl_xor_sync(0xFFFFFFFFu, s20, s);
            s1  += __shfl_xor_sync(0xFFFFFFFFu, s1,  s);
            s21 += __shfl_xor_sync(0xFFFFFFFFu, s21, s);
        }
        if (lane == 0) {
            int g0 = (m0 >> 3) + warpM * 4 + mt * 2;
            atomicAdd(&g_gsum [b * 32 + g0],     s0);
            atomicAdd(&g_gsum2[b * 32 + g0],     s20);
            atomicAdd(&g_gsum [b * 32 + g0 + 1], s1);
            atomicAdd(&g_gsum2[b * 32 + g0 + 1], s21);
        }
    }
}

// ================== kernel 4: finalize GroupNorm stats ==================
__global__ void k_finalize() {
    int i = threadIdx.x;   // 128 = B_*G_
    float inv_n = 1.0f / (8.0f * HW_);
    float mean = g_gsum[i] * inv_n;
    float var  = g_gsum2[i] * inv_n - mean * mean;
    g_mean[i] = mean;
    g_istd[i] = rsqrtf(var + EPS_);
}

// ================== kernel 5: normalize + affine + ReLU (float4) ==================
__global__ void k_norm(float* __restrict__ out,
                       const float* __restrict__ gamma,
                       const float* __restrict__ beta) {
    int idx = blockIdx.x * 256 + threadIdx.x;   // element-quad index
    float4 v = ((float4*)out)[idx];
    int e0 = idx << 2;
    int c  = (e0 >> 12) & 255;
    int bg = e0 >> 15;
    float sc = g_istd[bg] * gamma[c];
    float sh = beta[c] - g_mean[bg] * sc;
    v.x = fmaxf(fmaf(v.x, sc, sh), 0.0f);
    v.y = fmaxf(fmaf(v.y, sc, sh), 0.0f);
    v.z = fmaxf(fmaf(v.z, sc, sh), 0.0f);
    v.w = fmaxf(fmaf(v.w, sc, sh), 0.0f);
    ((float4*)out)[idx] = v;
}

// ================== launch ==================
extern "C" void kernel_launch(void* const* d_in, const int* in_sizes, int n_in,
                              void* d_out, int out_size) {
    const float* x     = (const float*)d_in[0];
    const float* off   = (const float*)d_in[1];
    const float* wgt   = (const float*)d_in[2];
    const float* attw  = (const float*)d_in[3];
    const float* attb  = (const float*)d_in[4];
    const float* gamma = (const float*)d_in[5];
    const float* beta  = (const float*)d_in[6];
    float* out = (float*)d_out;

    static bool configured = false;
    if (!configured) {
        cudaFuncSetAttribute(k_gemm, cudaFuncAttributeMaxDynamicSharedMemorySize, GEMM_SMEM);
        configured = true;
    }

    k_prep       <<<576 + 2304, 256>>>(off, wgt);
    k_xpose      <<<dim3(HW_ / 32, C_ / 32, B_), dim3(32, 8)>>>(x);
    k_im2col_att <<<dim3(HW_ / 8, B_), 256>>>(attw, attb);
    k_gemm       <<<dim3(NP_ / 128, 2), 256, GEMM_SMEM>>>(out);
    k_finalize   <<<1, B_ * G_>>>();
    k_norm       <<<(B_ * C_ * HW_) / 1024, 256>>>(out, gamma, beta);
}

// round 12
// speedup vs baseline: 1.1019x; 1.1019x over previous
#include <cuda_runtime.h>
#include <cuda_fp16.h>
#include <cstdint>

// Problem constants
#define B_   4
#define C_   256
#define H_   64
#define W_   64
#define HW_  4096
#define KK_  9
#define KD_  2304            // C*KK (GEMM K), reordered as k = kk*256 + c
#define NP_  16384           // B*HW (GEMM N)
#define G_   32
#define EPS_ 1e-5f

// ---------------- helpers ----------------
__device__ __forceinline__ uint32_t smem_to_u32(const void* p) {
    uint32_t a;
    asm("{ .reg .u64 t; cvta.to.shared.u64 t, %1; cvt.u32.u64 %0, t; }" : "=r"(a) : "l"(p));
    return a;
}
__device__ __forceinline__ void cp16(uint32_t saddr, const void* g) {
    asm volatile("cp.async.cg.shared.global [%0], [%1], 16;" :: "r"(saddr), "l"(g));
}
#define CP_COMMIT() asm volatile("cp.async.commit_group;" ::: "memory")
#define CP_WAIT(n)  asm volatile("cp.async.wait_group %0;" :: "n"(n) : "memory")

__device__ __forceinline__ void ldsm_x4(uint32_t* r, uint32_t addr) {
    asm volatile("ldmatrix.sync.aligned.m8n8.x4.shared.b16 {%0,%1,%2,%3}, [%4];"
                 : "=r"(r[0]), "=r"(r[1]), "=r"(r[2]), "=r"(r[3]) : "r"(addr));
}
__device__ __forceinline__ void mma_f16(float* d, const uint32_t* a, uint32_t b0, uint32_t b1) {
    asm volatile(
        "mma.sync.aligned.m16n8k16.row.col.f32.f16.f16.f32 "
        "{%0,%1,%2,%3}, {%4,%5,%6,%7}, {%8,%9}, {%0,%1,%2,%3};"
        : "+f"(d[0]), "+f"(d[1]), "+f"(d[2]), "+f"(d[3])
        : "r"(a[0]), "r"(a[1]), "r"(a[2]), "r"(a[3]), "r"(b0), "r"(b1));
}

// -------- scratch (device globals) --------
__device__ uint2   g_pos[B_ * KK_ * HW_];
__device__ float4  g_wt [B_ * KK_ * HW_];
__device__ __half  g_xt [(size_t)B_ * HW_ * C_];   // x transposed fp16: [b][hw][c], 8MB
__device__ __half  g_ah [C_ * KD_];                // weights fp16 [o][kk*256+c]
__device__ __half  g_bh [(size_t)NP_ * KD_];       // im2col fp16 [p][kk*256+c]
__device__ float   g_att[NP_];
__device__ float   g_gsum [B_ * G_];
__device__ float   g_gsum2[B_ * G_];
__device__ float   g_mean[B_ * G_];
__device__ float   g_istd[B_ * G_];

// ================== kernel 0: coords + weight convert merged ==================
__global__ void k_prep(const float* __restrict__ off, const float* __restrict__ wgt) {
    int bid = blockIdx.x;
    int tid = threadIdx.x;

    if (bid >= 576) {
        int wb = bid - 576;
        int o  = wb / 9;
        int kk = wb - o * 9;
        int c  = tid;
        g_ah[o * KD_ + kk * 256 + c] = __float2half_rn(wgt[(o * 256 + c) * 9 + kk]);
        return;
    }

    int bkk = bid >> 4;
    int hw  = (bid & 15) * 256 + tid;
    int b   = bkk / KK_;
    int kk  = bkk - b * KK_;
    int h   = hw >> 6;
    int w   = hw & 63;

    if (bid == 0) {
        if (tid < 128)      g_gsum [tid] = 0.0f;
        else                g_gsum2[tid - 128] = 0.0f;
    }

    float dy = off[(b * 18 + kk * 2    ) * HW_ + hw];
    float dx = off[(b * 18 + kk * 2 + 1) * HW_ + hw];

    float py = (float)h + (float)(kk / 3 - 1) + dy;
    float px = (float)w + (float)(kk % 3 - 1) + dx;

    float fy = floorf(py), fx = floorf(px);
    int iy0 = (int)fy, ix0 = (int)fx;
    float wy1 = py - fy, wy0 = 1.0f - wy1;
    float wx1 = px - fx, wx0 = 1.0f - wx1;

    bool vy0 = (iy0 >= 0)  && (iy0 < H_);
    bool vy1 = (iy0 >= -1) && (iy0 < H_ - 1);
    bool vx0 = (ix0 >= 0)  && (ix0 < W_);
    bool vx1 = (ix0 >= -1) && (ix0 < W_ - 1);

    float4 wt;
    wt.x = wy0 * wx0 * (float)(vy0 && vx0);
    wt.y = wy0 * wx1 * (float)(vy0 && vx1);
    wt.z = wy1 * wx0 * (float)(vy1 && vx0);
    wt.w = wy1 * wx1 * (float)(vy1 && vx1);

    int y0c = min(max(iy0, 0), H_ - 1);
    int y1c = min(max(iy0 + 1, 0), H_ - 1);
    int x0c = min(max(ix0, 0), W_ - 1);
    int x1c = min(max(ix0 + 1, 0), W_ - 1);

    unsigned p00 = (unsigned)(y0c * W_ + x0c);
    unsigned p01 = (unsigned)(y0c * W_ + x1c);
    unsigned p10 = (unsigned)(y1c * W_ + x0c);
    unsigned p11 = (unsigned)(y1c * W_ + x1c);

    int ci = bkk * HW_ + hw;
    g_pos[ci] = make_uint2(p00 | (p01 << 16), p10 | (p11 << 16));
    g_wt[ci]  = wt;
}

// ================== kernel 1: transpose x -> xT[b][hw][c] (fp16) ==================
__global__ void k_xpose(const float* __restrict__ x) {
    __shared__ float t[32][33];
    int b   = blockIdx.z;
    int hw0 = blockIdx.x * 32;
    int c0  = blockIdx.y * 32;
    int tx = threadIdx.x, ty = threadIdx.y;

    #pragma unroll
    for (int i = 0; i < 32; i += 8)
        t[ty + i][tx] = x[((size_t)(b * C_ + c0 + ty + i)) * HW_ + hw0 + tx];
    __syncthreads();
    #pragma unroll
    for (int i = 0; i < 32; i += 8)
        g_xt[((size_t)(b * HW_) + hw0 + ty + i) * C_ + c0 + tx] = __float2half_rn(t[tx][ty + i]);
}

// ================== kernel 2: im2col from fp16 xT + fused attention ==================
__global__ void k_im2col_att(const float* __restrict__ attw,
                             const float* __restrict__ attb) {
    __shared__ uint2  spos[8][KK_];
    __shared__ float4 swt [8][KK_];

    int b   = blockIdx.y;
    int hw0 = blockIdx.x * 8;
    int tid = threadIdx.x, wid = tid >> 5, lane = tid & 31;

    if (tid < 8 * KK_) {
        int pi = tid / KK_, kk = tid - pi * KK_;
        spos[pi][kk] = g_pos[(b * KK_ + kk) * HW_ + hw0 + pi];
        swt [pi][kk] = g_wt [(b * KK_ + kk) * HW_ + hw0 + pi];
    }
    __syncthreads();

    int p  = b * HW_ + hw0 + wid;
    int c8 = lane * 8;
    const __half* xtb = g_xt + (size_t)(b * HW_) * C_ + c8;
    __half* dst0 = g_bh + (size_t)p * KD_ + c8;

    float mx[8];
    #pragma unroll
    for (int j = 0; j < 8; ++j) mx[j] = -1e30f;

    #pragma unroll
    for (int kk = 0; kk < KK_; ++kk) {
        uint2 pos = spos[wid][kk];
        float4 wt = swt[wid][kk];
        uint4 ua = *(const uint4*)(xtb + (size_t)(pos.x & 0xFFFFu) * C_);
        uint4 ub = *(const uint4*)(xtb + (size_t)(pos.x >> 16)     * C_);
        uint4 uc = *(const uint4*)(xtb + (size_t)(pos.y & 0xFFFFu) * C_);
        uint4 ud = *(const uint4*)(xtb + (size_t)(pos.y >> 16)     * C_);
        const __half2* ha = (const __half2*)&ua;
        const __half2* hb = (const __half2*)&ub;
        const __half2* hc = (const __half2*)&uc;
        const __half2* hd = (const __half2*)&ud;

        float val[8];
        #pragma unroll
        for (int jj = 0; jj < 4; ++jj) {
            float2 fa = __half22float2(ha[jj]);
            float2 fb = __half22float2(hb[jj]);
            float2 fc = __half22float2(hc[jj]);
            float2 fd = __half22float2(hd[jj]);
            val[jj * 2]     = wt.x * fa.x + wt.y * fb.x + wt.z * fc.x + wt.w * fd.x;
            val[jj * 2 + 1] = wt.x * fa.y + wt.y * fb.y + wt.z * fc.y + wt.w * fd.y;
        }

        union { __half hh[8]; uint4 v; } u;
        #pragma unroll
        for (int j = 0; j < 8; ++j) {
            mx[j] = fmaxf(mx[j], val[j]);
            u.hh[j] = __float2half_rn(val[j]);
        }
        *(uint4*)(dst0 + kk * 256) = u.v;
    }

    float2 w0 = *(const float2*)&attw[c8];
    float2 w1 = *(const float2*)&attw[c8 + 2];
    float2 w2 = *(const float2*)&attw[c8 + 4];
    float2 w3 = *(const float2*)&attw[c8 + 6];
    float acc = w0.x * mx[0] + w0.y * mx[1] + w1.x * mx[2] + w1.y * mx[3]
              + w2.x * mx[4] + w2.y * mx[5] + w3.x * mx[6] + w3.y * mx[7];
    #pragma unroll
    for (int s = 16; s; s >>= 1) acc += __shfl_xor_sync(0xFFFFFFFFu, acc, s);
    if (lane == 0) g_att[p] = 1.0f / (1.0f + __expf(-(acc + attb[0])));
}

// ================== kernel 3: fp16 single-combo GEMM, 3 CTAs/SM ==================
// CTA 128(M) x 128(N), K-tile 32, 128 threads (2x2 warps, warp tile 64x64),
// 3-stage cp.async ring, 80B-padded rows, 3 CTAs/SM (12 warps).
// Stage: A[128x80B]=10240, B[128x80B]=10240 -> 20480B; 3 stages = 61440B.
#define STAGE_B 20480
#define GEMM_SMEM (3 * STAGE_B)

__global__ __launch_bounds__(128, 3) void k_gemm(float* __restrict__ out) {
    extern __shared__ __align__(128) char smem[];
    uint32_t sbase = smem_to_u32(smem);
    int tid = threadIdx.x, wid = tid >> 5, lane = tid & 31;
    int warpM = wid >> 1, warpN = wid & 1;
    int p0 = blockIdx.x * 128;
    int m0 = blockIdx.y * 128;

    // ---- loader: 128 threads; r = tid>>2 (0..31) row, q = tid&3 chunk; 4 row passes ----
    int r = tid >> 2, q = tid & 3;
    const __half* pA = g_ah + (size_t)(m0 + r) * KD_ + q * 8;
    const __half* pB = g_bh + (size_t)(p0 + r) * KD_ + q * 8;
    uint32_t sA = (uint32_t)(r * 80 + q * 16);
    const size_t GSTEP = (size_t)32 * KD_;

#define LOAD_STAGE(sb) do {                                          \
    _Pragma("unroll")                                                \
    for (int i = 0; i < 4; ++i) {                                    \
        uint32_t so = (sb) + sA + (uint32_t)(i * 2560);              \
        cp16(so,          pA + i * GSTEP);                           \
        cp16(so + 10240u, pB + i * GSTEP);                           \
    }                                                                \
    pA += 32; pB += 32;                                              \
    CP_COMMIT();                                                     \
} while (0)

    float acc[4][8][4];
    #pragma unroll
    for (int i = 0; i < 4; ++i)
        #pragma unroll
        for (int j = 0; j < 8; ++j)
            #pragma unroll
            for (int qq = 0; qq < 4; ++qq) acc[i][j][qq] = 0.0f;

    uint32_t laneoff = (uint32_t)((lane & 15) * 80 + ((lane >> 4) << 4));
    uint32_t aoff = (uint32_t)(warpM * 64 * 80) + laneoff;
    uint32_t boff = 10240u + (uint32_t)(warpN * 64 * 80) + laneoff;

    uint32_t cur = sbase;
    uint32_t nxt = sbase + 2u * STAGE_B;
    const uint32_t send = sbase + 3u * STAGE_B;

    LOAD_STAGE(sbase);
    LOAD_STAGE(sbase + STAGE_B);

    for (int kt = 0; kt < 72; ++kt) {
        if (kt < 70) { CP_WAIT(1); } else { CP_WAIT(0); }
        __syncthreads();
        if (kt < 70) {
            LOAD_STAGE(nxt);
            nxt += STAGE_B; if (nxt == send) nxt = sbase;
        }

        #pragma unroll
        for (int ks = 0; ks < 2; ++ks) {
            uint32_t ah[4][4], bh[4][4];
            #pragma unroll
            for (int mt = 0; mt < 4; ++mt)
                ldsm_x4(ah[mt], cur + aoff + (uint32_t)(mt * 16 * 80 + ks * 32));
            #pragma unroll
            for (int ntp = 0; ntp < 4; ++ntp)
                ldsm_x4(bh[ntp], cur + boff + (uint32_t)(ntp * 16 * 80 + ks * 32));

            #pragma unroll
            for (int mt = 0; mt < 4; ++mt)
                #pragma unroll
                for (int ntp = 0; ntp < 4; ++ntp)
                    #pragma unroll
                    for (int hf = 0; hf < 2; ++hf)
                        mma_f16(acc[mt][ntp * 2 + hf], ah[mt], bh[ntp][hf], bh[ntp][hf + 2]);
        }
        cur += STAGE_B; if (cur == send) cur = sbase;
    }

    // epilogue: multiply by att, write out, accumulate GroupNorm partial sums
    int b   = p0 >> 12;
    int hw0 = p0 & 4095;
    int qrow = lane >> 2, qcol = (lane & 3) * 2;

    #pragma unroll
    for (int mt = 0; mt < 4; ++mt) {
        float s0 = 0.0f, s20 = 0.0f, s1 = 0.0f, s21 = 0.0f;
        #pragma unroll
        for (int nt = 0; nt < 8; ++nt) {
            int n = warpN * 64 + nt * 8 + qcol;
            float2 av = *(const float2*)&g_att[p0 + n];
            int o = m0 + warpM * 64 + mt * 16 + qrow;
            float* base0 = out + ((size_t)(b * C_ + o)) * HW_ + hw0 + n;
            float* base1 = base0 + 8 * HW_;
            float2 v0, v1;
            v0.x = acc[mt][nt][0] * av.x;  v0.y = acc[mt][nt][1] * av.y;
            v1.x = acc[mt][nt][2] * av.x;  v1.y = acc[mt][nt][3] * av.y;
            *(float2*)base0 = v0;
            *(float2*)base1 = v1;
            s0 += v0.x + v0.y;  s20 += v0.x * v0.x + v0.y * v0.y;
            s1 += v1.x + v1.y;  s21 += v1.x * v1.x + v1.y * v1.y;
        }
        #pragma unroll
        for (int s = 16; s; s >>= 1) {
            s0  += __shfl_xor_sync(0xFFFFFFFFu, s0,  s);
            s20 += __shfl_xor_sync(0xFFFFFFFFu, s20, s);
            s1  += __shfl_xor_sync(0xFFFFFFFFu, s1,  s);
            s21 += __shfl_xor_sync(0xFFFFFFFFu, s21, s);
        }
        if (lane == 0) {
            int g0 = (m0 >> 3) + warpM * 8 + mt * 2;
            atomicAdd(&g_gsum [b * 32 + g0],     s0);
            atomicAdd(&g_gsum2[b * 32 + g0],     s20);
            atomicAdd(&g_gsum [b * 32 + g0 + 1], s1);
            atomicAdd(&g_gsum2[b * 32 + g0 + 1], s21);
        }
    }
}

// ================== kernel 4: finalize GroupNorm stats ==================
__global__ void k_finalize() {
    int i = threadIdx.x;   // 128 = B_*G_
    float inv_n = 1.0f / (8.0f * HW_);
    float mean = g_gsum[i] * inv_n;
    float var  = g_gsum2[i] * inv_n - mean * mean;
    g_mean[i] = mean;
    g_istd[i] = rsqrtf(var + EPS_);
}

// ================== kernel 5: normalize + affine + ReLU (float4) ==================
__global__ void k_norm(float* __restrict__ out,
                       const float* __restrict__ gamma,
                       const float* __restrict__ beta) {
    int idx = blockIdx.x * 256 + threadIdx.x;   // element-quad index
    float4 v = ((float4*)out)[idx];
    int e0 = idx << 2;
    int c  = (e0 >> 12) & 255;
    int bg = e0 >> 15;
    float sc = g_istd[bg] * gamma[c];
    float sh = beta[c] - g_mean[bg] * sc;
    v.x = fmaxf(fmaf(v.x, sc, sh), 0.0f);
    v.y = fmaxf(fmaf(v.y, sc, sh), 0.0f);
    v.z = fmaxf(fmaf(v.z, sc, sh), 0.0f);
    v.w = fmaxf(fmaf(v.w, sc, sh), 0.0f);
    ((float4*)out)[idx] = v;
}

// ================== launch ==================
extern "C" void kernel_launch(void* const* d_in, const int* in_sizes, int n_in,
                              void* d_out, int out_size) {
    const float* x     = (const float*)d_in[0];
    const float* off   = (const float*)d_in[1];
    const float* wgt   = (const float*)d_in[2];
    const float* attw  = (const float*)d_in[3];
    const float* attb  = (const float*)d_in[4];
    const float* gamma = (const float*)d_in[5];
    const float* beta  = (const float*)d_in[6];
    float* out = (float*)d_out;

    static bool configured = false;
    if (!configured) {
        cudaFuncSetAttribute(k_gemm, cudaFuncAttributeMaxDynamicSharedMemorySize, GEMM_SMEM);
        configured = true;
    }

    k_prep       <<<576 + 2304, 256>>>(off, wgt);
    k_xpose      <<<dim3(HW_ / 32, C_ / 32, B_), dim3(32, 8)>>>(x);
    k_im2col_att <<<dim3(HW_ / 8, B_), 256>>>(attw, attb);
    k_gemm       <<<dim3(NP_ / 128, 2), 128, GEMM_SMEM>>>(out);
    k_finalize   <<<1, B_ * G_>>>();
    k_norm       <<<(B_ * C_ * HW_) / 1024, 256>>>(out, gamma, beta);
}

// round 13
// speedup vs baseline: 1.2058x; 1.0942x over previous
#include <cuda_runtime.h>
#include <cuda_fp16.h>
#include <cstdint>

// Problem constants
#define B_   4
#define C_   256
#define H_   64
#define W_   64
#define HW_  4096
#define KK_  9
#define KD_  2304            // C*KK (GEMM K), reordered as k = kk*256 + c
#define NP_  16384           // B*HW (GEMM N)
#define G_   32
#define EPS_ 1e-5f

// ---------------- helpers ----------------
__device__ __forceinline__ uint32_t smem_to_u32(const void* p) {
    uint32_t a;
    asm("{ .reg .u64 t; cvta.to.shared.u64 t, %1; cvt.u32.u64 %0, t; }" : "=r"(a) : "l"(p));
    return a;
}
__device__ __forceinline__ void cp16(uint32_t saddr, const void* g) {
    asm volatile("cp.async.cg.shared.global [%0], [%1], 16;" :: "r"(saddr), "l"(g));
}
#define CP_COMMIT() asm volatile("cp.async.commit_group;" ::: "memory")
#define CP_WAIT(n)  asm volatile("cp.async.wait_group %0;" :: "n"(n) : "memory")

__device__ __forceinline__ void ldsm_x4(uint32_t* r, uint32_t addr) {
    asm volatile("ldmatrix.sync.aligned.m8n8.x4.shared.b16 {%0,%1,%2,%3}, [%4];"
                 : "=r"(r[0]), "=r"(r[1]), "=r"(r[2]), "=r"(r[3]) : "r"(addr));
}
__device__ __forceinline__ void mma_f16(float* d, const uint32_t* a, uint32_t b0, uint32_t b1) {
    asm volatile(
        "mma.sync.aligned.m16n8k16.row.col.f32.f16.f16.f32 "
        "{%0,%1,%2,%3}, {%4,%5,%6,%7}, {%8,%9}, {%0,%1,%2,%3};"
        : "+f"(d[0]), "+f"(d[1]), "+f"(d[2]), "+f"(d[3])
        : "r"(a[0]), "r"(a[1]), "r"(a[2]), "r"(a[3]), "r"(b0), "r"(b1));
}

// -------- scratch (device globals) --------
__device__ uint2   g_pos[B_ * KK_ * HW_];
__device__ float4  g_wt [B_ * KK_ * HW_];
__device__ __half  g_xt [(size_t)B_ * HW_ * C_];   // x transposed fp16: [b][hw][c], 8MB
__device__ __half  g_ah [C_ * KD_];                // weights fp16 [o][kk*256+c]
__device__ __half  g_bh [(size_t)NP_ * KD_];       // im2col fp16 [p][kk*256+c]
__device__ float   g_att[NP_];
__device__ float   g_gsum [B_ * G_];
__device__ float   g_gsum2[B_ * G_];
__device__ float   g_mean[B_ * G_];
__device__ float   g_istd[B_ * G_];

// ================== kernel 0: coords + weight convert merged ==================
__global__ void k_prep(const float* __restrict__ off, const float* __restrict__ wgt) {
    int bid = blockIdx.x;
    int tid = threadIdx.x;

    if (bid >= 576) {
        int wb = bid - 576;
        int o  = wb / 9;
        int kk = wb - o * 9;
        int c  = tid;
        g_ah[o * KD_ + kk * 256 + c] = __float2half_rn(wgt[(o * 256 + c) * 9 + kk]);
        return;
    }

    int bkk = bid >> 4;
    int hw  = (bid & 15) * 256 + tid;
    int b   = bkk / KK_;
    int kk  = bkk - b * KK_;
    int h   = hw >> 6;
    int w   = hw & 63;

    if (bid == 0) {
        if (tid < 128)      g_gsum [tid] = 0.0f;
        else                g_gsum2[tid - 128] = 0.0f;
    }

    float dy = off[(b * 18 + kk * 2    ) * HW_ + hw];
    float dx = off[(b * 18 + kk * 2 + 1) * HW_ + hw];

    float py = (float)h + (float)(kk / 3 - 1) + dy;
    float px = (float)w + (float)(kk % 3 - 1) + dx;

    float fy = floorf(py), fx = floorf(px);
    int iy0 = (int)fy, ix0 = (int)fx;
    float wy1 = py - fy, wy0 = 1.0f - wy1;
    float wx1 = px - fx, wx0 = 1.0f - wx1;

    bool vy0 = (iy0 >= 0)  && (iy0 < H_);
    bool vy1 = (iy0 >= -1) && (iy0 < H_ - 1);
    bool vx0 = (ix0 >= 0)  && (ix0 < W_);
    bool vx1 = (ix0 >= -1) && (ix0 < W_ - 1);

    float4 wt;
    wt.x = wy0 * wx0 * (float)(vy0 && vx0);
    wt.y = wy0 * wx1 * (float)(vy0 && vx1);
    wt.z = wy1 * wx0 * (float)(vy1 && vx0);
    wt.w = wy1 * wx1 * (float)(vy1 && vx1);

    int y0c = min(max(iy0, 0), H_ - 1);
    int y1c = min(max(iy0 + 1, 0), H_ - 1);
    int x0c = min(max(ix0, 0), W_ - 1);
    int x1c = min(max(ix0 + 1, 0), W_ - 1);

    unsigned p00 = (unsigned)(y0c * W_ + x0c);
    unsigned p01 = (unsigned)(y0c * W_ + x1c);
    unsigned p10 = (unsigned)(y1c * W_ + x0c);
    unsigned p11 = (unsigned)(y1c * W_ + x1c);

    int ci = bkk * HW_ + hw;
    g_pos[ci] = make_uint2(p00 | (p01 << 16), p10 | (p11 << 16));
    g_wt[ci]  = wt;
}

// ================== kernel 1: transpose x -> xT[b][hw][c] (fp16) ==================
__global__ void k_xpose(const float* __restrict__ x) {
    __shared__ float t[32][33];
    int b   = blockIdx.z;
    int hw0 = blockIdx.x * 32;
    int c0  = blockIdx.y * 32;
    int tx = threadIdx.x, ty = threadIdx.y;

    #pragma unroll
    for (int i = 0; i < 32; i += 8)
        t[ty + i][tx] = x[((size_t)(b * C_ + c0 + ty + i)) * HW_ + hw0 + tx];
    __syncthreads();
    #pragma unroll
    for (int i = 0; i < 32; i += 8)
        g_xt[((size_t)(b * HW_) + hw0 + ty + i) * C_ + c0 + tx] = __float2half_rn(t[tx][ty + i]);
}

// ================== kernel 2: im2col from fp16 xT + fused attention ==================
__global__ void k_im2col_att(const float* __restrict__ attw,
                             const float* __restrict__ attb) {
    __shared__ uint2  spos[8][KK_];
    __shared__ float4 swt [8][KK_];

    int b   = blockIdx.y;
    int hw0 = blockIdx.x * 8;
    int tid = threadIdx.x, wid = tid >> 5, lane = tid & 31;

    if (tid < 8 * KK_) {
        int pi = tid / KK_, kk = tid - pi * KK_;
        spos[pi][kk] = g_pos[(b * KK_ + kk) * HW_ + hw0 + pi];
        swt [pi][kk] = g_wt [(b * KK_ + kk) * HW_ + hw0 + pi];
    }
    __syncthreads();

    int p  = b * HW_ + hw0 + wid;
    int c8 = lane * 8;
    const __half* xtb = g_xt + (size_t)(b * HW_) * C_ + c8;
    __half* dst0 = g_bh + (size_t)p * KD_ + c8;

    float mx[8];
    #pragma unroll
    for (int j = 0; j < 8; ++j) mx[j] = -1e30f;

    #pragma unroll
    for (int kk = 0; kk < KK_; ++kk) {
        uint2 pos = spos[wid][kk];
        float4 wt = swt[wid][kk];
        uint4 ua = *(const uint4*)(xtb + (size_t)(pos.x & 0xFFFFu) * C_);
        uint4 ub = *(const uint4*)(xtb + (size_t)(pos.x >> 16)     * C_);
        uint4 uc = *(const uint4*)(xtb + (size_t)(pos.y & 0xFFFFu) * C_);
        uint4 ud = *(const uint4*)(xtb + (size_t)(pos.y >> 16)     * C_);
        const __half2* ha = (const __half2*)&ua;
        const __half2* hb = (const __half2*)&ub;
        const __half2* hc = (const __half2*)&uc;
        const __half2* hd = (const __half2*)&ud;

        float val[8];
        #pragma unroll
        for (int jj = 0; jj < 4; ++jj) {
            float2 fa = __half22float2(ha[jj]);
            float2 fb = __half22float2(hb[jj]);
            float2 fc = __half22float2(hc[jj]);
            float2 fd = __half22float2(hd[jj]);
            val[jj * 2]     = wt.x * fa.x + wt.y * fb.x + wt.z * fc.x + wt.w * fd.x;
            val[jj * 2 + 1] = wt.x * fa.y + wt.y * fb.y + wt.z * fc.y + wt.w * fd.y;
        }

        union { __half hh[8]; uint4 v; } u;
        #pragma unroll
        for (int j = 0; j < 8; ++j) {
            mx[j] = fmaxf(mx[j], val[j]);
            u.hh[j] = __float2half_rn(val[j]);
        }
        *(uint4*)(dst0 + kk * 256) = u.v;
    }

    float2 w0 = *(const float2*)&attw[c8];
    float2 w1 = *(const float2*)&attw[c8 + 2];
    float2 w2 = *(const float2*)&attw[c8 + 4];
    float2 w3 = *(const float2*)&attw[c8 + 6];
    float acc = w0.x * mx[0] + w0.y * mx[1] + w1.x * mx[2] + w1.y * mx[3]
              + w2.x * mx[4] + w2.y * mx[5] + w3.x * mx[6] + w3.y * mx[7];
    #pragma unroll
    for (int s = 16; s; s >>= 1) acc += __shfl_xor_sync(0xFFFFFFFFu, acc, s);
    if (lane == 0) g_att[p] = 1.0f / (1.0f + __expf(-(acc + attb[0])));
}

// ================== kernel 3: fp16 GEMM, software-pipelined fragments ==================
// CTA 128(M) x 128(N), K-tile 32, 128 threads (2x2 warps, warp tile 64x64),
// 4-stage cp.async ring, 80B-padded rows, 2 CTAs/SM,
// double-buffered register fragments (LDSM for next ks overlaps current MMAs).
#define STAGE_B 20480
#define NSTAGE  4
#define GEMM_SMEM (NSTAGE * STAGE_B)

__global__ __launch_bounds__(128, 2) void k_gemm(float* __restrict__ out) {
    extern __shared__ __align__(128) char smem[];
    uint32_t sbase = smem_to_u32(smem);
    int tid = threadIdx.x, wid = tid >> 5, lane = tid & 31;
    int warpM = wid >> 1, warpN = wid & 1;
    int p0 = blockIdx.x * 128;
    int m0 = blockIdx.y * 128;

    // ---- loader: 128 threads; r = tid>>2 (0..31) row, q = tid&3 chunk; 4 row passes ----
    int r = tid >> 2, q = tid & 3;
    const __half* pA = g_ah + (size_t)(m0 + r) * KD_ + q * 8;
    const __half* pB = g_bh + (size_t)(p0 + r) * KD_ + q * 8;
    uint32_t sA = (uint32_t)(r * 80 + q * 16);
    const size_t GSTEP = (size_t)32 * KD_;

#define LOAD_STAGE(sb) do {                                          \
    _Pragma("unroll")                                                \
    for (int i = 0; i < 4; ++i) {                                    \
        uint32_t so = (sb) + sA + (uint32_t)(i * 2560);              \
        cp16(so,          pA + i * GSTEP);                           \
        cp16(so + 10240u, pB + i * GSTEP);                           \
    }                                                                \
    pA += 32; pB += 32;                                              \
    CP_COMMIT();                                                     \
} while (0)

    float acc[4][8][4];
    #pragma unroll
    for (int i = 0; i < 4; ++i)
        #pragma unroll
        for (int j = 0; j < 8; ++j)
            #pragma unroll
            for (int qq = 0; qq < 4; ++qq) acc[i][j][qq] = 0.0f;

    uint32_t laneoff = (uint32_t)((lane & 15) * 80 + ((lane >> 4) << 4));
    uint32_t aoff = (uint32_t)(warpM * 64 * 80) + laneoff;
    uint32_t boff = 10240u + (uint32_t)(warpN * 64 * 80) + laneoff;

    uint32_t stg[NSTAGE];
    #pragma unroll
    for (int s = 0; s < NSTAGE; ++s) stg[s] = sbase + (uint32_t)s * STAGE_B;

    // fragment double buffers
    uint32_t ah[2][4][4], bh[2][4][4];

#define LOAD_FRAGS(buf, st, ks) do {                                               \
    _Pragma("unroll")                                                              \
    for (int mt = 0; mt < 4; ++mt)                                                 \
        ldsm_x4(ah[buf][mt], (st) + aoff + (uint32_t)(mt * 16 * 80 + (ks) * 32));  \
    _Pragma("unroll")                                                              \
    for (int ntp = 0; ntp < 4; ++ntp)                                              \
        ldsm_x4(bh[buf][ntp], (st) + boff + (uint32_t)(ntp * 16 * 80 + (ks) * 32));\
} while (0)

    // prime: 3 stages in flight
    LOAD_STAGE(stg[0]);
    LOAD_STAGE(stg[1]);
    LOAD_STAGE(stg[2]);

    CP_WAIT(2);                 // stage 0 complete
    __syncthreads();
    LOAD_FRAGS(0, stg[0], 0);   // frags for (kt=0, ks=0)

    for (int kt = 0; kt < 72; ++kt) {
        // stages <= kt+1 complete after this wait (loads for kt+3 not yet issued)
        if (kt < 69) { CP_WAIT(1); } else { CP_WAIT(0); }
        __syncthreads();
        if (kt + 3 < 72) LOAD_STAGE(stg[(kt + 3) & 3]);

        uint32_t cur = stg[kt & 3];
        #pragma unroll
        for (int ks = 0; ks < 2; ++ks) {
            int step = kt * 2 + ks;
            int cb = step & 1, nb = cb ^ 1;
            // prefetch next ks-slice's fragments (overlaps with MMAs below)
            if (ks == 0) {
                LOAD_FRAGS(nb, cur, 1);
            } else if (kt < 71) {
                LOAD_FRAGS(nb, stg[(kt + 1) & 3], 0);
            }
            #pragma unroll
            for (int mt = 0; mt < 4; ++mt)
                #pragma unroll
                for (int ntp = 0; ntp < 4; ++ntp)
                    #pragma unroll
                    for (int hf = 0; hf < 2; ++hf)
                        mma_f16(acc[mt][ntp * 2 + hf], ah[cb][mt],
                                bh[cb][ntp][hf], bh[cb][ntp][hf + 2]);
        }
    }

    // epilogue: multiply by att, write out, accumulate GroupNorm partial sums
    int b   = p0 >> 12;
    int hw0 = p0 & 4095;
    int qrow = lane >> 2, qcol = (lane & 3) * 2;

    #pragma unroll
    for (int mt = 0; mt < 4; ++mt) {
        float s0 = 0.0f, s20 = 0.0f, s1 = 0.0f, s21 = 0.0f;
        #pragma unroll
        for (int nt = 0; nt < 8; ++nt) {
            int n = warpN * 64 + nt * 8 + qcol;
            float2 av = *(const float2*)&g_att[p0 + n];
            int o = m0 + warpM * 64 + mt * 16 + qrow;
            float* base0 = out + ((size_t)(b * C_ + o)) * HW_ + hw0 + n;
            float* base1 = base0 + 8 * HW_;
            float2 v0, v1;
            v0.x = acc[mt][nt][0] * av.x;  v0.y = acc[mt][nt][1] * av.y;
            v1.x = acc[mt][nt][2] * av.x;  v1.y = acc[mt][nt][3] * av.y;
            *(float2*)base0 = v0;
            *(float2*)base1 = v1;
            s0 += v0.x + v0.y;  s20 += v0.x * v0.x + v0.y * v0.y;
            s1 += v1.x + v1.y;  s21 += v1.x * v1.x + v1.y * v1.y;
        }
        #pragma unroll
        for (int s = 16; s; s >>= 1) {
            s0  += __shfl_xor_sync(0xFFFFFFFFu, s0,  s);
            s20 += __shfl_xor_sync(0xFFFFFFFFu, s20, s);
            s1  += __shfl_xor_sync(0xFFFFFFFFu, s1,  s);
            s21 += __shfl_xor_sync(0xFFFFFFFFu, s21, s);
        }
        if (lane == 0) {
            int g0 = (m0 >> 3) + warpM * 8 + mt * 2;
            atomicAdd(&g_gsum [b * 32 + g0],     s0);
            atomicAdd(&g_gsum2[b * 32 + g0],     s20);
            atomicAdd(&g_gsum [b * 32 + g0 + 1], s1);
            atomicAdd(&g_gsum2[b * 32 + g0 + 1], s21);
        }
    }
}

// ================== kernel 4: finalize GroupNorm stats ==================
__global__ void k_finalize() {
    int i = threadIdx.x;   // 128 = B_*G_
    float inv_n = 1.0f / (8.0f * HW_);
    float mean = g_gsum[i] * inv_n;
    float var  = g_gsum2[i] * inv_n - mean * mean;
    g_mean[i] = mean;
    g_istd[i] = rsqrtf(var + EPS_);
}

// ================== kernel 5: normalize + affine + ReLU (float4) ==================
__global__ void k_norm(float* __restrict__ out,
                       const float* __restrict__ gamma,
                       const float* __restrict__ beta) {
    int idx = blockIdx.x * 256 + threadIdx.x;   // element-quad index
    float4 v = ((float4*)out)[idx];
    int e0 = idx << 2;
    int c  = (e0 >> 12) & 255;
    int bg = e0 >> 15;
    float sc = g_istd[bg] * gamma[c];
    float sh = beta[c] - g_mean[bg] * sc;
    v.x = fmaxf(fmaf(v.x, sc, sh), 0.0f);
    v.y = fmaxf(fmaf(v.y, sc, sh), 0.0f);
    v.z = fmaxf(fmaf(v.z, sc, sh), 0.0f);
    v.w = fmaxf(fmaf(v.w, sc, sh), 0.0f);
    ((float4*)out)[idx] = v;
}

// ================== launch ==================
extern "C" void kernel_launch(void* const* d_in, const int* in_sizes, int n_in,
                              void* d_out, int out_size) {
    const float* x     = (const float*)d_in[0];
    const float* off   = (const float*)d_in[1];
    const float* wgt   = (const float*)d_in[2];
    const float* attw  = (const float*)d_in[3];
    const float* attb  = (const float*)d_in[4];
    const float* gamma = (const float*)d_in[5];
    const float* beta  = (const float*)d_in[6];
    float* out = (float*)d_out;

    static bool configured = false;
    if (!configured) {
        cudaFuncSetAttribute(k_gemm, cudaFuncAttributeMaxDynamicSharedMemorySize, GEMM_SMEM);
        configured = true;
    }

    k_prep       <<<576 + 2304, 256>>>(off, wgt);
    k_xpose      <<<dim3(HW_ / 32, C_ / 32, B_), dim3(32, 8)>>>(x);
    k_im2col_att <<<dim3(HW_ / 8, B_), 256>>>(attw, attb);
    k_gemm       <<<dim3(NP_ / 128, 2), 128, GEMM_SMEM>>>(out);
    k_finalize   <<<1, B_ * G_>>>();
    k_norm       <<<(B_ * C_ * HW_) / 1024, 256>>>(out, gamma, beta);
}

// round 14
// speedup vs baseline: 1.2487x; 1.0356x over previous
#include <cuda_runtime.h>
#include <cuda_fp16.h>
#include <cstdint>

// Problem constants
#define B_   4
#define C_   256
#define H_   64
#define W_   64
#define HW_  4096
#define KK_  9
#define KD_  2304            // C*KK (GEMM K), reordered as k = kk*256 + c
#define NP_  16384           // B*HW (GEMM N)
#define G_   32
#define EPS_ 1e-5f

// ---------------- helpers ----------------
__device__ __forceinline__ uint32_t smem_to_u32(const void* p) {
    uint32_t a;
    asm("{ .reg .u64 t; cvta.to.shared.u64 t, %1; cvt.u32.u64 %0, t; }" : "=r"(a) : "l"(p));
    return a;
}
__device__ __forceinline__ void cp16(uint32_t saddr, const void* g) {
    asm volatile("cp.async.cg.shared.global [%0], [%1], 16;" :: "r"(saddr), "l"(g));
}
#define CP_COMMIT() asm volatile("cp.async.commit_group;" ::: "memory")
#define CP_WAIT(n)  asm volatile("cp.async.wait_group %0;" :: "n"(n) : "memory")

__device__ __forceinline__ void ldsm_x4(uint32_t* r, uint32_t addr) {
    asm volatile("ldmatrix.sync.aligned.m8n8.x4.shared.b16 {%0,%1,%2,%3}, [%4];"
                 : "=r"(r[0]), "=r"(r[1]), "=r"(r[2]), "=r"(r[3]) : "r"(addr));
}
__device__ __forceinline__ void mma_f16(float* d, const uint32_t* a, uint32_t b0, uint32_t b1) {
    asm volatile(
        "mma.sync.aligned.m16n8k16.row.col.f32.f16.f16.f32 "
        "{%0,%1,%2,%3}, {%4,%5,%6,%7}, {%8,%9}, {%0,%1,%2,%3};"
        : "+f"(d[0]), "+f"(d[1]), "+f"(d[2]), "+f"(d[3])
        : "r"(a[0]), "r"(a[1]), "r"(a[2]), "r"(a[3]), "r"(b0), "r"(b1));
}

// -------- scratch (device globals) --------
__device__ uint2   g_pos[B_ * KK_ * HW_];
__device__ float4  g_wt [B_ * KK_ * HW_];
__device__ __half  g_xt [(size_t)B_ * HW_ * C_];   // x transposed fp16: [b][hw][c], 8MB
__device__ __half  g_ah [C_ * KD_];                // weights fp16 [o][kk*256+c]
__device__ __half  g_bh [(size_t)NP_ * KD_];       // im2col fp16 [p][kk*256+c]
__device__ float   g_att[NP_];
__device__ float   g_gsum [B_ * G_];
__device__ float   g_gsum2[B_ * G_];

// ================== kernel 0: coords + weight convert + transpose, one launch ==================
// blocks [0, 576): coords; [576, 2880): weight convert; [2880, 6976): x transpose
__global__ void k_prep(const float* __restrict__ off, const float* __restrict__ wgt,
                       const float* __restrict__ x) {
    __shared__ float t[32][33];
    int bid = blockIdx.x;
    int tid = threadIdx.x;

    if (bid >= 2880) {
        // ---- transpose x -> xT[b][hw][c] fp16 ----
        int xb = bid - 2880;            // 0..4095
        int b    = xb >> 10;
        int rest = xb & 1023;
        int c0   = (rest >> 7) << 5;    // 8 c-tiles
        int hw0  = (rest & 127) << 5;   // 128 hw-tiles
        int tx = tid & 31, ty = tid >> 5;

        #pragma unroll
        for (int i = 0; i < 32; i += 8)
            t[ty + i][tx] = x[((size_t)(b * C_ + c0 + ty + i)) * HW_ + hw0 + tx];
        __syncthreads();
        #pragma unroll
        for (int i = 0; i < 32; i += 8)
            g_xt[((size_t)(b * HW_) + hw0 + ty + i) * C_ + c0 + tx] = __float2half_rn(t[tx][ty + i]);
        return;
    }

    if (bid >= 576) {
        // ---- weight convert ----
        int wb = bid - 576;
        int o  = wb / 9;
        int kk = wb - o * 9;
        int c  = tid;
        g_ah[o * KD_ + kk * 256 + c] = __float2half_rn(wgt[(o * 256 + c) * 9 + kk]);
        return;
    }

    // ---- coords ----
    int bkk = bid >> 4;
    int hw  = (bid & 15) * 256 + tid;
    int b   = bkk / KK_;
    int kk  = bkk - b * KK_;
    int h   = hw >> 6;
    int w   = hw & 63;

    if (bid == 0) {
        if (tid < 128)      g_gsum [tid] = 0.0f;
        else                g_gsum2[tid - 128] = 0.0f;
    }

    float dy = off[(b * 18 + kk * 2    ) * HW_ + hw];
    float dx = off[(b * 18 + kk * 2 + 1) * HW_ + hw];

    float py = (float)h + (float)(kk / 3 - 1) + dy;
    float px = (float)w + (float)(kk % 3 - 1) + dx;

    float fy = floorf(py), fx = floorf(px);
    int iy0 = (int)fy, ix0 = (int)fx;
    float wy1 = py - fy, wy0 = 1.0f - wy1;
    float wx1 = px - fx, wx0 = 1.0f - wx1;

    bool vy0 = (iy0 >= 0)  && (iy0 < H_);
    bool vy1 = (iy0 >= -1) && (iy0 < H_ - 1);
    bool vx0 = (ix0 >= 0)  && (ix0 < W_);
    bool vx1 = (ix0 >= -1) && (ix0 < W_ - 1);

    float4 wt;
    wt.x = wy0 * wx0 * (float)(vy0 && vx0);
    wt.y = wy0 * wx1 * (float)(vy0 && vx1);
    wt.z = wy1 * wx0 * (float)(vy1 && vx0);
    wt.w = wy1 * wx1 * (float)(vy1 && vx1);

    int y0c = min(max(iy0, 0), H_ - 1);
    int y1c = min(max(iy0 + 1, 0), H_ - 1);
    int x0c = min(max(ix0, 0), W_ - 1);
    int x1c = min(max(ix0 + 1, 0), W_ - 1);

    unsigned p00 = (unsigned)(y0c * W_ + x0c);
    unsigned p01 = (unsigned)(y0c * W_ + x1c);
    unsigned p10 = (unsigned)(y1c * W_ + x0c);
    unsigned p11 = (unsigned)(y1c * W_ + x1c);

    int ci = bkk * HW_ + hw;
    g_pos[ci] = make_uint2(p00 | (p01 << 16), p10 | (p11 << 16));
    g_wt[ci]  = wt;
}

// ================== kernel 1: im2col from fp16 xT + fused attention ==================
__global__ void k_im2col_att(const float* __restrict__ attw,
                             const float* __restrict__ attb) {
    __shared__ uint2  spos[8][KK_];
    __shared__ float4 swt [8][KK_];

    int b   = blockIdx.y;
    int hw0 = blockIdx.x * 8;
    int tid = threadIdx.x, wid = tid >> 5, lane = tid & 31;

    if (tid < 8 * KK_) {
        int pi = tid / KK_, kk = tid - pi * KK_;
        spos[pi][kk] = g_pos[(b * KK_ + kk) * HW_ + hw0 + pi];
        swt [pi][kk] = g_wt [(b * KK_ + kk) * HW_ + hw0 + pi];
    }
    __syncthreads();

    int p  = b * HW_ + hw0 + wid;
    int c8 = lane * 8;
    const __half* xtb = g_xt + (size_t)(b * HW_) * C_ + c8;
    __half* dst0 = g_bh + (size_t)p * KD_ + c8;

    float mx[8];
    #pragma unroll
    for (int j = 0; j < 8; ++j) mx[j] = -1e30f;

    #pragma unroll
    for (int kk = 0; kk < KK_; ++kk) {
        uint2 pos = spos[wid][kk];
        float4 wt = swt[wid][kk];
        uint4 ua = *(const uint4*)(xtb + (size_t)(pos.x & 0xFFFFu) * C_);
        uint4 ub = *(const uint4*)(xtb + (size_t)(pos.x >> 16)     * C_);
        uint4 uc = *(const uint4*)(xtb + (size_t)(pos.y & 0xFFFFu) * C_);
        uint4 ud = *(const uint4*)(xtb + (size_t)(pos.y >> 16)     * C_);
        const __half2* ha = (const __half2*)&ua;
        const __half2* hb = (const __half2*)&ub;
        const __half2* hc = (const __half2*)&uc;
        const __half2* hd = (const __half2*)&ud;

        float val[8];
        #pragma unroll
        for (int jj = 0; jj < 4; ++jj) {
            float2 fa = __half22float2(ha[jj]);
            float2 fb = __half22float2(hb[jj]);
            float2 fc = __half22float2(hc[jj]);
            float2 fd = __half22float2(hd[jj]);
            val[jj * 2]     = wt.x * fa.x + wt.y * fb.x + wt.z * fc.x + wt.w * fd.x;
            val[jj * 2 + 1] = wt.x * fa.y + wt.y * fb.y + wt.z * fc.y + wt.w * fd.y;
        }

        union { __half hh[8]; uint4 v; } u;
        #pragma unroll
        for (int j = 0; j < 8; ++j) {
            mx[j] = fmaxf(mx[j], val[j]);
            u.hh[j] = __float2half_rn(val[j]);
        }
        *(uint4*)(dst0 + kk * 256) = u.v;
    }

    float2 w0 = *(const float2*)&attw[c8];
    float2 w1 = *(const float2*)&attw[c8 + 2];
    float2 w2 = *(const float2*)&attw[c8 + 4];
    float2 w3 = *(const float2*)&attw[c8 + 6];
    float acc = w0.x * mx[0] + w0.y * mx[1] + w1.x * mx[2] + w1.y * mx[3]
              + w2.x * mx[4] + w2.y * mx[5] + w3.x * mx[6] + w3.y * mx[7];
    #pragma unroll
    for (int s = 16; s; s >>= 1) acc += __shfl_xor_sync(0xFFFFFFFFu, acc, s);
    if (lane == 0) g_att[p] = 1.0f / (1.0f + __expf(-(acc + attb[0])));
}

// ================== kernel 2: fp16 GEMM, interleaved LDSM/MMA pipeline ==================
// CTA 128(M) x 128(N), K-tile 32, 128 threads (2x2 warps, warp tile 64x64),
// 4-stage cp.async ring, 80B-padded rows, 2 CTAs/SM,
// double-buffered register fragments with 2-LDSM/8-MMA interleave.
#define STAGE_B 20480
#define NSTAGE  4
#define GEMM_SMEM (NSTAGE * STAGE_B)

__global__ __launch_bounds__(128, 2) void k_gemm(float* __restrict__ out) {
    extern __shared__ __align__(128) char smem[];
    uint32_t sbase = smem_to_u32(smem);
    int tid = threadIdx.x, wid = tid >> 5, lane = tid & 31;
    int warpM = wid >> 1, warpN = wid & 1;
    int p0 = blockIdx.x * 128;
    int m0 = blockIdx.y * 128;

    // ---- loader: 128 threads; r = tid>>2 (0..31) row, q = tid&3 chunk; 4 row passes ----
    int r = tid >> 2, q = tid & 3;
    const __half* pA = g_ah + (size_t)(m0 + r) * KD_ + q * 8;
    const __half* pB = g_bh + (size_t)(p0 + r) * KD_ + q * 8;
    uint32_t sA = (uint32_t)(r * 80 + q * 16);
    const size_t GSTEP = (size_t)32 * KD_;

#define LOAD_STAGE(sb) do {                                          \
    _Pragma("unroll")                                                \
    for (int i = 0; i < 4; ++i) {                                    \
        uint32_t so = (sb) + sA + (uint32_t)(i * 2560);              \
        cp16(so,          pA + i * GSTEP);                           \
        cp16(so + 10240u, pB + i * GSTEP);                           \
    }                                                                \
    pA += 32; pB += 32;                                              \
    CP_COMMIT();                                                     \
} while (0)

    float acc[4][8][4];
    #pragma unroll
    for (int i = 0; i < 4; ++i)
        #pragma unroll
        for (int j = 0; j < 8; ++j)
            #pragma unroll
            for (int qq = 0; qq < 4; ++qq) acc[i][j][qq] = 0.0f;

    uint32_t laneoff = (uint32_t)((lane & 15) * 80 + ((lane >> 4) << 4));
    uint32_t aoff = (uint32_t)(warpM * 64 * 80) + laneoff;
    uint32_t boff = 10240u + (uint32_t)(warpN * 64 * 80) + laneoff;

    uint32_t stg[NSTAGE];
    #pragma unroll
    for (int s = 0; s < NSTAGE; ++s) stg[s] = sbase + (uint32_t)s * STAGE_B;

    // fragment double buffers
    uint32_t ah[2][4][4], bh[2][4][4];

    // prime: 3 stages in flight
    LOAD_STAGE(stg[0]);
    LOAD_STAGE(stg[1]);
    LOAD_STAGE(stg[2]);

    CP_WAIT(2);                 // stage 0 complete
    __syncthreads();
    #pragma unroll
    for (int g = 0; g < 4; ++g) {       // frags for (kt=0, ks=0)
        ldsm_x4(ah[0][g], stg[0] + aoff + (uint32_t)(g * 16 * 80));
        ldsm_x4(bh[0][g], stg[0] + boff + (uint32_t)(g * 16 * 80));
    }

    for (int kt = 0; kt < 72; ++kt) {
        // stages <= kt+1 complete after this wait (loads for kt+3 not yet issued)
        if (kt < 69) { CP_WAIT(1); } else { CP_WAIT(0); }
        __syncthreads();
        if (kt + 3 < 72) LOAD_STAGE(stg[(kt + 3) & 3]);

        uint32_t cur = stg[kt & 3];
        #pragma unroll
        for (int ks = 0; ks < 2; ++ks) {
            int step = kt * 2 + ks;
            int cb = step & 1, nb = cb ^ 1;
            // prefetch source for next ks-slice's fragments
            uint32_t pst = (ks == 0) ? cur : stg[(kt + 1) & 3];
            uint32_t pko = (ks == 0) ? 32u : 0u;
            bool doPf = (ks == 0) || (kt < 71);

            #pragma unroll
            for (int grp = 0; grp < 4; ++grp) {
                if (doPf) {   // 2 LDSM interleaved with each 8-MMA group
                    ldsm_x4(ah[nb][grp], pst + aoff + (uint32_t)(grp * 16 * 80) + pko);
                    ldsm_x4(bh[nb][grp], pst + boff + (uint32_t)(grp * 16 * 80) + pko);
                }
                #pragma unroll
                for (int ntp = 0; ntp < 4; ++ntp)
                    #pragma unroll
                    for (int hf = 0; hf < 2; ++hf)
                        mma_f16(acc[grp][ntp * 2 + hf], ah[cb][grp],
                                bh[cb][ntp][hf], bh[cb][ntp][hf + 2]);
            }
        }
    }

    // epilogue: multiply by att, write out, accumulate GroupNorm partial sums
    int b   = p0 >> 12;
    int hw0 = p0 & 4095;
    int qrow = lane >> 2, qcol = (lane & 3) * 2;

    #pragma unroll
    for (int mt = 0; mt < 4; ++mt) {
        float s0 = 0.0f, s20 = 0.0f, s1 = 0.0f, s21 = 0.0f;
        #pragma unroll
        for (int nt = 0; nt < 8; ++nt) {
            int n = warpN * 64 + nt * 8 + qcol;
            float2 av = *(const float2*)&g_att[p0 + n];
            int o = m0 + warpM * 64 + mt * 16 + qrow;
            float* base0 = out + ((size_t)(b * C_ + o)) * HW_ + hw0 + n;
            float* base1 = base0 + 8 * HW_;
            float2 v0, v1;
            v0.x = acc[mt][nt][0] * av.x;  v0.y = acc[mt][nt][1] * av.y;
            v1.x = acc[mt][nt][2] * av.x;  v1.y = acc[mt][nt][3] * av.y;
            *(float2*)base0 = v0;
            *(float2*)base1 = v1;
            s0 += v0.x + v0.y;  s20 += v0.x * v0.x + v0.y * v0.y;
            s1 += v1.x + v1.y;  s21 += v1.x * v1.x + v1.y * v1.y;
        }
        #pragma unroll
        for (int s = 16; s; s >>= 1) {
            s0  += __shfl_xor_sync(0xFFFFFFFFu, s0,  s);
            s20 += __shfl_xor_sync(0xFFFFFFFFu, s20, s);
            s1  += __shfl_xor_sync(0xFFFFFFFFu, s1,  s);
            s21 += __shfl_xor_sync(0xFFFFFFFFu, s21, s);
        }
        if (lane == 0) {
            int g0 = (m0 >> 3) + warpM * 8 + mt * 2;
            atomicAdd(&g_gsum [b * 32 + g0],     s0);
            atomicAdd(&g_gsum2[b * 32 + g0],     s20);
            atomicAdd(&g_gsum [b * 32 + g0 + 1], s1);
            atomicAdd(&g_gsum2[b * 32 + g0 + 1], s21);
        }
    }
}

// ================== kernel 3: GroupNorm finalize + normalize + affine + ReLU ==================
// 4096 blocks x 256 threads x 4 elements; each block lies within one (b,g,c).
__global__ void k_norm(float* __restrict__ out,
                       const float* __restrict__ gamma,
                       const float* __restrict__ beta) {
    __shared__ float s_sc, s_sh;
    int blk = blockIdx.x;
    int tid = threadIdx.x;

    if (tid == 0) {
        int bg = blk >> 5;
        int c  = (blk >> 2) & 255;
        float inv_n = 1.0f / (8.0f * HW_);
        float mean = g_gsum[bg] * inv_n;
        float var  = g_gsum2[bg] * inv_n - mean * mean;
        float istd = rsqrtf(var + EPS_);
        float sc = istd * gamma[c];
        s_sc = sc;
        s_sh = beta[c] - mean * sc;
    }
    __syncthreads();

    float sc = s_sc, sh = s_sh;
    int idx = blk * 256 + tid;
    float4 v = ((float4*)out)[idx];
    v.x = fmaxf(fmaf(v.x, sc, sh), 0.0f);
    v.y = fmaxf(fmaf(v.y, sc, sh), 0.0f);
    v.z = fmaxf(fmaf(v.z, sc, sh), 0.0f);
    v.w = fmaxf(fmaf(v.w, sc, sh), 0.0f);
    ((float4*)out)[idx] = v;
}

// ================== launch ==================
extern "C" void kernel_launch(void* const* d_in, const int* in_sizes, int n_in,
                              void* d_out, int out_size) {
    const float* x     = (const float*)d_in[0];
    const float* off   = (const float*)d_in[1];
    const float* wgt   = (const float*)d_in[2];
    const float* attw  = (const float*)d_in[3];
    const float* attb  = (const float*)d_in[4];
    const float* gamma = (const float*)d_in[5];
    const float* beta  = (const float*)d_in[6];
    float* out = (float*)d_out;

    static bool configured = false;
    if (!configured) {
        cudaFuncSetAttribute(k_gemm, cudaFuncAttributeMaxDynamicSharedMemorySize, GEMM_SMEM);
        configured = true;
    }

    k_prep       <<<2880 + 4096, 256>>>(off, wgt, x);
    k_im2col_att <<<dim3(HW_ / 8, B_), 256>>>(attw, attb);
    k_gemm       <<<dim3(NP_ / 128, 2), 128, GEMM_SMEM>>>(out);
    k_norm       <<<(B_ * C_ * HW_) / 1024, 256>>>(out, gamma, beta);
}